// round 2
// baseline (speedup 1.0000x reference)
#include <cuda_runtime.h>
#include <math.h>

// ---------------- problem constants ----------------
#define S_   2
#define C_   256
#define KD_  128
#define CE_  16
#define F_   5
#define HW_  2304           // 48*48
#define LK_  (F_*HW_)       // 11520
#define TAU_INV 30.0f

// ---------------- scratch (device globals; no allocs allowed) ----------------
__device__ float g_wq [S_*HW_*KD_];   // self wq == wk (l2-normalized K-proj of tgt)
__device__ float g_wv [S_*HW_*C_];    // self V-proj
__device__ float g_y  [S_*C_*HW_];    // self-attn out + residual, layout [s][c][p]
__device__ float g_wq2[S_*HW_*KD_];   // cross q (instnorm folded)
__device__ float g_wk2[S_*LK_*KD_];   // cross k
__device__ float g_wv2[S_*LK_*CE_];   // cross v
__device__ float g_mu [S_*C_];
__device__ float g_rs [S_*C_];
__device__ float g_wf [S_*KD_*C_];    // folded WK_cross * rstd
__device__ float g_bf [S_*KD_];

// =====================================================================
// Generic projection: out[s][p][j] = (opt l2norm_j)( sum_i in(s,i,p)*W[j][i] + b[j] )
// MODE 0: in[(s*Cin+i)*P + p]           (tgt / g_y)
// MODE 1: in[((f*2+s)*Cin+i)*HW + hw]   (memory / pos_enc), f=p/HW, hw=p%HW
// J in {16,128,256}; 256 threads; 16 rows per block.
// =====================================================================
template<int J, int MODE, bool NORM>
__global__ void proj_kernel(const float* __restrict__ in, const float* __restrict__ W,
                            const float* __restrict__ B, float* __restrict__ out,
                            int Cin, int P, int wstride, int bstride)
{
    constexpr int PB = 16;
    constexpr int PperT = J / 16;          // rows handled per thread
    const int s  = blockIdx.y;
    const int p0 = blockIdx.x * PB;
    const int tid = threadIdx.x;

    __shared__ float shIn[256 * 16];
    __shared__ float shOut[16 * J];
    __shared__ float shNorm[16];

    // stage input tile [Cin][16]
    for (int idx = tid; idx < Cin * PB; idx += 256) {
        int i = idx >> 4, pl = idx & 15, p = p0 + pl;
        long off;
        if (MODE == 0) {
            off = ((long)(s * Cin + i)) * P + p;
        } else {
            int f = p / HW_, hw = p - f * HW_;
            off = ((long)((f * 2 + s) * Cin + i)) * HW_ + hw;
        }
        shIn[idx] = in[off];
    }
    __syncthreads();

    const int j  = tid % J;
    const int pg = tid / J;
    const int pbase = pg * PperT;

    float acc[PperT];
#pragma unroll
    for (int u = 0; u < PperT; u++) acc[u] = 0.f;

    const float* Wr = W + (long)s * wstride + (long)j * Cin;
#pragma unroll 2
    for (int i4 = 0; i4 < Cin; i4 += 4) {
        float4 w4 = *reinterpret_cast<const float4*>(Wr + i4);
        float wv[4] = {w4.x, w4.y, w4.z, w4.w};
#pragma unroll
        for (int qi = 0; qi < 4; qi++) {
            const float* row = shIn + (i4 + qi) * 16 + pbase;
            if (PperT >= 4) {
#pragma unroll
                for (int u4 = 0; u4 < PperT; u4 += 4) {
                    float4 v = *reinterpret_cast<const float4*>(row + u4);
                    acc[u4+0] += wv[qi] * v.x;
                    acc[u4+1] += wv[qi] * v.y;
                    acc[u4+2] += wv[qi] * v.z;
                    acc[u4+3] += wv[qi] * v.w;
                }
            } else {
#pragma unroll
                for (int u = 0; u < PperT; u++) acc[u] += wv[qi] * row[u];
            }
        }
    }

    const float b = B[(long)s * bstride + j];

    if (NORM) {
#pragma unroll
        for (int u = 0; u < PperT; u++)
            shOut[(pbase + u) * J + j] = acc[u] + b;
        __syncthreads();
        if (tid < PB) {
            float ss = 0.f;
            int off = (tid * 2) & (J - 1);      // stagger to avoid bank conflicts
            for (int jj = 0; jj < J; jj++) {
                int jc = jj + off; if (jc >= J) jc -= J;
                float v = shOut[tid * J + jc];
                ss += v * v;
            }
            shNorm[tid] = 1.f / fmaxf(sqrtf(ss), 1e-12f);
        }
        __syncthreads();
#pragma unroll
        for (int u = 0; u < PperT; u++) {
            int p = p0 + pbase + u;
            out[((long)s * P + p) * J + j] = shOut[(pbase + u) * J + j] * shNorm[pbase + u];
        }
    } else {
#pragma unroll
        for (int u = 0; u < PperT; u++) {
            int p = p0 + pbase + u;
            out[((long)s * P + p) * J + j] = acc[u] + b;
        }
    }
}

// =====================================================================
// Self flash-attention: 32 queries/block, key tiles of 64, dv=256.
// y[s][i][p] = softmax(wq·wkᵀ * 30) @ wv  + tgt[s][i][p]
// thread t: q = t>>3, g = t&7; owns output dims i = g*4 + 32*m (m=0..7).
// =====================================================================
__global__ void self_attn_kernel(const float* __restrict__ wq, const float* __restrict__ wv,
                                 const float* __restrict__ tgt, float* __restrict__ y)
{
    extern __shared__ float sm[];
    float* shQ  = sm;                    // 32 x 132
    float* shK  = shQ + 32 * 132;        // 64 x 132
    float* shV  = shK + 64 * 132;        // 64 x 256
    float* shP  = shV + 64 * 256;        // 32 x 65
    float* shR1 = shP + 32 * 65;         // 256
    float* shR2 = shR1 + 256;            // 256

    const int s   = blockIdx.y;
    const int q0  = blockIdx.x * 32;
    const int tid = threadIdx.x;
    const int q   = tid >> 3;
    const int g   = tid & 7;

    const float* wqs = wq + (long)s * HW_ * KD_;
    const float* wvs = wv + (long)s * HW_ * C_;

    // stage Q tile
    for (int idx = tid; idx < 32 * 32; idx += 256) {
        int r = idx >> 5, c4 = idx & 31;
        float4 v = *reinterpret_cast<const float4*>(wqs + (long)(q0 + r) * KD_ + c4 * 4);
        *reinterpret_cast<float4*>(shQ + r * 132 + c4 * 4) = v;
    }

    float m_run = -1e30f, l_run = 0.f;
    float4 acc[8];
#pragma unroll
    for (int m = 0; m < 8; m++) acc[m] = make_float4(0.f, 0.f, 0.f, 0.f);

    for (int kt = 0; kt < HW_ / 64; kt++) {
        const int k0 = kt * 64;
        __syncthreads();
        // stage K tile
        for (int idx = tid; idx < 64 * 32; idx += 256) {
            int r = idx >> 5, c4 = idx & 31;
            float4 v = *reinterpret_cast<const float4*>(wqs + (long)(k0 + r) * KD_ + c4 * 4);
            *reinterpret_cast<float4*>(shK + r * 132 + c4 * 4) = v;
        }
        // stage V tile
        for (int idx = tid; idx < 64 * 64; idx += 256) {
            int r = idx >> 6, c4 = idx & 63;
            float4 v = *reinterpret_cast<const float4*>(wvs + (long)(k0 + r) * C_ + c4 * 4);
            *reinterpret_cast<float4*>(shV + r * 256 + c4 * 4) = v;
        }
        __syncthreads();

        // scores: thread handles keys k = g + 8*kk
        float s8[8];
#pragma unroll
        for (int kk = 0; kk < 8; kk++) s8[kk] = 0.f;
        const float* qrow = shQ + q * 132;
#pragma unroll 4
        for (int dc = 0; dc < 32; dc++) {
            float4 qv = *reinterpret_cast<const float4*>(qrow + dc * 4);
#pragma unroll
            for (int kk = 0; kk < 8; kk++) {
                float4 kv = *reinterpret_cast<const float4*>(shK + (g + 8 * kk) * 132 + dc * 4);
                s8[kk] += qv.x * kv.x + qv.y * kv.y + qv.z * kv.z + qv.w * kv.w;
            }
        }
        float lm = -1e30f;
#pragma unroll
        for (int kk = 0; kk < 8; kk++) { s8[kk] *= TAU_INV; lm = fmaxf(lm, s8[kk]); }
        shR1[tid] = lm;
        __syncthreads();
        float tm = lm;
#pragma unroll
        for (int gg = 0; gg < 8; gg++) tm = fmaxf(tm, shR1[q * 8 + gg]);
        float m_new = fmaxf(m_run, tm);
        float alpha = __expf(m_run - m_new);
        float psum = 0.f;
#pragma unroll
        for (int kk = 0; kk < 8; kk++) {
            float pe = __expf(s8[kk] - m_new);
            shP[q * 65 + g + 8 * kk] = pe;
            psum += pe;
        }
        shR2[tid] = psum;
        __syncthreads();
        float Ssum = 0.f;
#pragma unroll
        for (int gg = 0; gg < 8; gg++) Ssum += shR2[q * 8 + gg];
        l_run = l_run * alpha + Ssum;
        m_run = m_new;
#pragma unroll
        for (int m = 0; m < 8; m++) {
            acc[m].x *= alpha; acc[m].y *= alpha; acc[m].z *= alpha; acc[m].w *= alpha;
        }
        const float* prow = shP + q * 65;
#pragma unroll 2
        for (int kk = 0; kk < 64; kk++) {
            float pk = prow[kk];
            const float* vrow = shV + kk * 256 + g * 4;
#pragma unroll
            for (int m = 0; m < 8; m++) {
                float4 vv = *reinterpret_cast<const float4*>(vrow + m * 32);
                acc[m].x += pk * vv.x; acc[m].y += pk * vv.y;
                acc[m].z += pk * vv.z; acc[m].w += pk * vv.w;
            }
        }
    }

    const float inv_l = 1.f / l_run;
    const int p = q0 + q;
#pragma unroll
    for (int m = 0; m < 8; m++) {
        int i = g * 4 + 32 * m;
        long base = ((long)(s * C_ + i)) * HW_ + p;
        y[base          ] = acc[m].x * inv_l + tgt[base          ];
        y[base +   HW_  ] = acc[m].y * inv_l + tgt[base +   HW_  ];
        y[base + 2*HW_  ] = acc[m].z * inv_l + tgt[base + 2*HW_  ];
        y[base + 3*HW_  ] = acc[m].w * inv_l + tgt[base + 3*HW_  ];
    }
}

// =====================================================================
// InstanceNorm statistics over spatial axis (per s,c)
// =====================================================================
__global__ void instnorm_stats_kernel(const float* __restrict__ y,
                                      float* __restrict__ mu, float* __restrict__ rs)
{
    const int sc = blockIdx.x;                 // 0..511
    const float* row = y + (long)sc * HW_;
    float sum = 0.f, ss = 0.f;
    for (int p = threadIdx.x; p < HW_; p += 256) {
        float v = row[p];
        sum += v; ss += v * v;
    }
    __shared__ float s1[256], s2[256];
    s1[threadIdx.x] = sum; s2[threadIdx.x] = ss;
    __syncthreads();
    for (int st = 128; st > 0; st >>= 1) {
        if (threadIdx.x < st) {
            s1[threadIdx.x] += s1[threadIdx.x + st];
            s2[threadIdx.x] += s2[threadIdx.x + st];
        }
        __syncthreads();
    }
    if (threadIdx.x == 0) {
        float m = s1[0] / (float)HW_;
        float var = s2[0] / (float)HW_ - m * m;
        mu[sc] = m;
        rs[sc] = rsqrtf(var + 1e-5f);
    }
}

// =====================================================================
// Fold instancenorm into cross-K weights: Wf[s][j][i] = WK[j][i]*rs;
// bf[s][j] = bK[j] - sum_i mu*rs*WK[j][i]
// =====================================================================
__global__ void fold_kernel(const float* __restrict__ WK, const float* __restrict__ bK,
                            const float* __restrict__ mu, const float* __restrict__ rs,
                            float* __restrict__ Wf, float* __restrict__ bf)
{
    const int j = blockIdx.x, s = blockIdx.y, tid = threadIdx.x;   // tid = i (256)
    float w = WK[j * C_ + tid] * rs[s * C_ + tid];
    Wf[((long)(s * KD_ + j)) * C_ + tid] = w;
    __shared__ float red[256];
    red[tid] = w * mu[s * C_ + tid];
    __syncthreads();
    for (int st = 128; st > 0; st >>= 1) {
        if (tid < st) red[tid] += red[tid + st];
        __syncthreads();
    }
    if (tid == 0) bf[s * KD_ + j] = bK[j] - red[0];
}

// =====================================================================
// Cross flash-attention: 32 queries/block, key tiles of 64, dv=16.
// out[s][i][p] layout = final output [1,S,16,h,w].
// thread t: q = t>>3, g = t&7; owns output dims i = 2g, 2g+1.
// =====================================================================
__global__ void cross_attn_kernel(const float* __restrict__ wq2, const float* __restrict__ wk2,
                                  const float* __restrict__ wv2, float* __restrict__ out)
{
    extern __shared__ float sm[];
    float* shQ  = sm;                    // 32 x 132
    float* shK  = shQ + 32 * 132;        // 64 x 132
    float* shV  = shK + 64 * 132;        // 64 x 16
    float* shP  = shV + 64 * 16;         // 32 x 65
    float* shR1 = shP + 32 * 65;
    float* shR2 = shR1 + 256;

    const int s   = blockIdx.y;
    const int q0  = blockIdx.x * 32;
    const int tid = threadIdx.x;
    const int q   = tid >> 3;
    const int g   = tid & 7;

    const float* wqs = wq2 + (long)s * HW_ * KD_;
    const float* wks = wk2 + (long)s * LK_ * KD_;
    const float* wvs = wv2 + (long)s * LK_ * CE_;

    for (int idx = tid; idx < 32 * 32; idx += 256) {
        int r = idx >> 5, c4 = idx & 31;
        float4 v = *reinterpret_cast<const float4*>(wqs + (long)(q0 + r) * KD_ + c4 * 4);
        *reinterpret_cast<float4*>(shQ + r * 132 + c4 * 4) = v;
    }

    float m_run = -1e30f, l_run = 0.f;
    float2 acc = make_float2(0.f, 0.f);

    for (int kt = 0; kt < LK_ / 64; kt++) {
        const int k0 = kt * 64;
        __syncthreads();
        for (int idx = tid; idx < 64 * 32; idx += 256) {
            int r = idx >> 5, c4 = idx & 31;
            float4 v = *reinterpret_cast<const float4*>(wks + (long)(k0 + r) * KD_ + c4 * 4);
            *reinterpret_cast<float4*>(shK + r * 132 + c4 * 4) = v;
        }
        for (int idx = tid; idx < 64 * 4; idx += 256) {
            int r = idx >> 2, c4 = idx & 3;
            float4 v = *reinterpret_cast<const float4*>(wvs + (long)(k0 + r) * CE_ + c4 * 4);
            *reinterpret_cast<float4*>(shV + r * 16 + c4 * 4) = v;
        }
        __syncthreads();

        float s8[8];
#pragma unroll
        for (int kk = 0; kk < 8; kk++) s8[kk] = 0.f;
        const float* qrow = shQ + q * 132;
#pragma unroll 4
        for (int dc = 0; dc < 32; dc++) {
            float4 qv = *reinterpret_cast<const float4*>(qrow + dc * 4);
#pragma unroll
            for (int kk = 0; kk < 8; kk++) {
                float4 kv = *reinterpret_cast<const float4*>(shK + (g + 8 * kk) * 132 + dc * 4);
                s8[kk] += qv.x * kv.x + qv.y * kv.y + qv.z * kv.z + qv.w * kv.w;
            }
        }
        float lm = -1e30f;
#pragma unroll
        for (int kk = 0; kk < 8; kk++) { s8[kk] *= TAU_INV; lm = fmaxf(lm, s8[kk]); }
        shR1[tid] = lm;
        __syncthreads();
        float tm = lm;
#pragma unroll
        for (int gg = 0; gg < 8; gg++) tm = fmaxf(tm, shR1[q * 8 + gg]);
        float m_new = fmaxf(m_run, tm);
        float alpha = __expf(m_run - m_new);
        float psum = 0.f;
#pragma unroll
        for (int kk = 0; kk < 8; kk++) {
            float pe = __expf(s8[kk] - m_new);
            shP[q * 65 + g + 8 * kk] = pe;
            psum += pe;
        }
        shR2[tid] = psum;
        __syncthreads();
        float Ssum = 0.f;
#pragma unroll
        for (int gg = 0; gg < 8; gg++) Ssum += shR2[q * 8 + gg];
        l_run = l_run * alpha + Ssum;
        m_run = m_new;
        acc.x *= alpha; acc.y *= alpha;
        const float* prow = shP + q * 65;
#pragma unroll 4
        for (int kk = 0; kk < 64; kk++) {
            float pk = prow[kk];
            float2 vv = *reinterpret_cast<const float2*>(shV + kk * 16 + g * 2);
            acc.x += pk * vv.x; acc.y += pk * vv.y;
        }
    }

    const float inv_l = 1.f / l_run;
    const int p = q0 + q;
    const int i0 = 2 * g;
    out[((long)(s * CE_ + i0    )) * HW_ + p] = acc.x * inv_l;
    out[((long)(s * CE_ + i0 + 1)) * HW_ + p] = acc.y * inv_l;
}

// =====================================================================
// Launcher
// =====================================================================
extern "C" void kernel_launch(void* const* d_in, const int* in_sizes, int n_in,
                              void* d_out, int out_size)
{
    const float* tgt    = (const float*)d_in[0];
    const float* memory = (const float*)d_in[1];
    const float* pos    = (const float*)d_in[2];
    const float* WKs_w  = (const float*)d_in[3];
    const float* WKs_b  = (const float*)d_in[4];
    const float* WVs_w  = (const float*)d_in[5];
    const float* WVs_b  = (const float*)d_in[6];
    const float* WKc_w  = (const float*)d_in[7];
    const float* WKc_b  = (const float*)d_in[8];
    const float* WVc_w  = (const float*)d_in[9];
    const float* WVc_b  = (const float*)d_in[10];
    float* out = (float*)d_out;

    float *p_wq, *p_wv, *p_y, *p_wq2, *p_wk2, *p_wv2, *p_mu, *p_rs, *p_wf, *p_bf;
    cudaGetSymbolAddress((void**)&p_wq,  g_wq);
    cudaGetSymbolAddress((void**)&p_wv,  g_wv);
    cudaGetSymbolAddress((void**)&p_y,   g_y);
    cudaGetSymbolAddress((void**)&p_wq2, g_wq2);
    cudaGetSymbolAddress((void**)&p_wk2, g_wk2);
    cudaGetSymbolAddress((void**)&p_wv2, g_wv2);
    cudaGetSymbolAddress((void**)&p_mu,  g_mu);
    cudaGetSymbolAddress((void**)&p_rs,  g_rs);
    cudaGetSymbolAddress((void**)&p_wf,  g_wf);
    cudaGetSymbolAddress((void**)&p_bf,  g_bf);

    const int SELF_SH  = (32*132 + 64*132 + 64*256 + 32*65 + 512) * 4;   // ~126.6 KB
    const int CROSS_SH = (32*132 + 64*132 + 64*16  + 32*65 + 512) * 4;   // ~65.2 KB
    cudaFuncSetAttribute(self_attn_kernel,  cudaFuncAttributeMaxDynamicSharedMemorySize, SELF_SH);
    cudaFuncSetAttribute(cross_attn_kernel, cudaFuncAttributeMaxDynamicSharedMemorySize, CROSS_SH);

    // 1) self projections
    proj_kernel<128, 0, true ><<<dim3(HW_/16, S_), 256>>>(tgt, WKs_w, WKs_b, p_wq, C_, HW_, 0, 0);
    proj_kernel<256, 0, false><<<dim3(HW_/16, S_), 256>>>(tgt, WVs_w, WVs_b, p_wv, C_, HW_, 0, 0);
    // 2) self flash attention + residual  -> g_y [s][c][p]
    self_attn_kernel<<<dim3(HW_/32, S_), 256, SELF_SH>>>(p_wq, p_wv, tgt, p_y);
    // 3) instance norm stats + fold into cross-K weights
    instnorm_stats_kernel<<<S_*C_, 256>>>(p_y, p_mu, p_rs);
    fold_kernel<<<dim3(KD_, S_), 256>>>(WKc_w, WKc_b, p_mu, p_rs, p_wf, p_bf);
    // 4) cross projections
    proj_kernel<128, 0, true ><<<dim3(HW_/16, S_), 256>>>(p_y, p_wf, p_bf, p_wq2, C_, HW_, KD_*C_, KD_);
    proj_kernel<128, 1, true ><<<dim3(LK_/16, S_), 256>>>(memory, WKc_w, WKc_b, p_wk2, C_, LK_, 0, 0);
    proj_kernel<16,  1, false><<<dim3(LK_/16, S_), 256>>>(pos, WVc_w, WVc_b, p_wv2, CE_, LK_, 0, 0);
    // 5) cross flash attention -> output [1,S,16,h,w]
    cross_attn_kernel<<<dim3(HW_/32, S_), 256, CROSS_SH>>>(p_wq2, p_wk2, p_wv2, out);
}

// round 4
// speedup vs baseline: 2.1208x; 2.1208x over previous
#include <cuda_runtime.h>
#include <math.h>

// ---------------- problem constants ----------------
#define S_   2
#define C_   256
#define KD_  128
#define CE_  16
#define F_   5
#define HW_  2304           // 48*48
#define LK_  (F_*HW_)       // 11520
#define TAU_INV 30.0f

typedef unsigned long long u64;

// ---------------- f32x2 packed helpers ----------------
__device__ __forceinline__ u64 pack2(float x) {
    u64 r; asm("mov.b64 %0, {%1, %1};" : "=l"(r) : "f"(x)); return r;
}
__device__ __forceinline__ void unpack2(u64 v, float &x, float &y) {
    asm("mov.b64 {%0, %1}, %2;" : "=f"(x), "=f"(y) : "l"(v));
}
__device__ __forceinline__ void fma2(u64 &d, u64 a, u64 b) {
    asm("fma.rn.f32x2 %0, %1, %2, %0;" : "+l"(d) : "l"(a), "l"(b));
}
__device__ __forceinline__ u64 add2(u64 a, u64 b) {
    u64 r; asm("add.rn.f32x2 %0, %1, %2;" : "=l"(r) : "l"(a), "l"(b)); return r;
}

// ---------------- cp.async helpers ----------------
__device__ __forceinline__ void cp16(float* dst, const float* src) {
    unsigned sa = (unsigned)__cvta_generic_to_shared(dst);
    asm volatile("cp.async.cg.shared.global [%0], [%1], 16;" :: "r"(sa), "l"(src));
}
__device__ __forceinline__ void cp8(float* dst, const float* src) {
    unsigned sa = (unsigned)__cvta_generic_to_shared(dst);
    asm volatile("cp.async.ca.shared.global [%0], [%1], 8;" :: "r"(sa), "l"(src));
}
#define CP_COMMIT() asm volatile("cp.async.commit_group;" ::: "memory")
#define CP_WAIT1()  asm volatile("cp.async.wait_group 1;" ::: "memory")

// ---------------- scratch (device globals; no allocs allowed) ----------------
__device__ float g_wq [S_*HW_*KD_];   // self wq == wk, [s][p][128], l2-normalized
__device__ float g_wv [S_*HW_*C_];    // self V-proj [s][p][256]
__device__ float g_y  [S_*C_*HW_];    // self-attn out + residual, [s][c][p]
__device__ float g_wq2[S_*HW_*KD_];   // cross q [s][p][128]
__device__ float g_wk2[S_*LK_*KD_];   // cross k [s][k][128]
__device__ float g_wv2[S_*LK_*CE_];   // cross v [s][k][16]
__device__ float g_mu [S_*C_];
__device__ float g_rs [S_*C_];
__device__ float g_wf [S_*KD_*C_];    // folded WK_cross * rstd
__device__ float g_bf [S_*KD_];

// =====================================================================
// Generic projection: val(s,p,j) = (opt l2norm_j)( sum_i in(s,i,p)*W[j][i] + b[j] )
// MODE 0: in[(s*Cin+i)*P + p]           (tgt / g_y)
// MODE 1: in[((f*2+s)*Cin+i)*HW + hw]   (memory / pos_enc), f=p/HW, hw=p%HW
// out[(s*P+p)*J + j].   f32x2 inner for PperT>=2.
// =====================================================================
template<int J, int MODE, bool NORM>
__global__ void proj_kernel(const float* __restrict__ in, const float* __restrict__ W,
                            const float* __restrict__ B, float* __restrict__ out,
                            int Cin, int P, int wstride, int bstride)
{
    constexpr int PB = 16;
    constexpr int PperT = J / 16;
    const int s  = blockIdx.y;
    const int p0 = blockIdx.x * PB;
    const int tid = threadIdx.x;

    __shared__ float shIn[256 * 16];
    __shared__ float shOut[16 * J];
    __shared__ float shNorm[16];

    // stage input tile [Cin][16]
    for (int idx = tid; idx < Cin * PB; idx += 256) {
        int i = idx >> 4, pl = idx & 15, p = p0 + pl;
        long off;
        if (MODE == 0) {
            off = ((long)(s * Cin + i)) * P + p;
        } else {
            int f = p / HW_, hw = p - f * HW_;
            off = ((long)((f * 2 + s) * Cin + i)) * HW_ + hw;
        }
        shIn[idx] = in[off];
    }
    __syncthreads();

    const int j  = tid % J;
    const int pg = tid / J;
    const int pbase = pg * PperT;
    const float b = B[(long)s * bstride + j];
    const float* Wr = W + (long)s * wstride + (long)j * Cin;

    if (PperT >= 2) {
        constexpr int NU = (PperT >= 2) ? PperT / 2 : 1;
        u64 acc2[NU];
#pragma unroll
        for (int u = 0; u < NU; u++) acc2[u] = 0ull;

#pragma unroll 2
        for (int i4 = 0; i4 < Cin; i4 += 4) {
            float4 w4 = *reinterpret_cast<const float4*>(Wr + i4);
            float wv[4] = {w4.x, w4.y, w4.z, w4.w};
#pragma unroll
            for (int qi = 0; qi < 4; qi++) {
                u64 wp = pack2(wv[qi]);
                const u64* row = reinterpret_cast<const u64*>(shIn + (i4 + qi) * 16 + pbase);
#pragma unroll
                for (int u = 0; u < NU; u++) fma2(acc2[u], wp, row[u]);
            }
        }

        if (NORM) {
#pragma unroll
            for (int u = 0; u < NU; u++) {
                float x, y; unpack2(acc2[u], x, y);
                shOut[(pbase + 2*u    ) * J + j] = x + b;
                shOut[(pbase + 2*u + 1) * J + j] = y + b;
            }
            __syncthreads();
            if (tid < PB) {
                float ss = 0.f;
                int off = (tid * 2) & (J - 1);
                for (int jj = 0; jj < J; jj++) {
                    int jc = jj + off; if (jc >= J) jc -= J;
                    float v = shOut[tid * J + jc];
                    ss += v * v;
                }
                shNorm[tid] = 1.f / fmaxf(sqrtf(ss), 1e-12f);
            }
            __syncthreads();
#pragma unroll
            for (int u = 0; u < PperT; u++) {
                int p = p0 + pbase + u;
                out[((long)s * P + p) * J + j] = shOut[(pbase + u) * J + j] * shNorm[pbase + u];
            }
        } else {
#pragma unroll
            for (int u = 0; u < NU; u++) {
                float x, y; unpack2(acc2[u], x, y);
                int p = p0 + pbase + 2*u;
                out[((long)s * P + p    ) * J + j] = x + b;
                out[((long)s * P + p + 1) * J + j] = y + b;
            }
        }
    } else {
        // scalar path (J=16, PperT=1)
        float acc = 0.f;
#pragma unroll 4
        for (int i = 0; i < Cin; i++)
            acc += Wr[i] * shIn[i * 16 + pbase];
        int p = p0 + pbase;
        out[((long)s * P + p) * J + j] = acc + b;
    }
}

// =====================================================================
// Self flash-attention (fixed-max softmax: p = exp(s - 30)).
// Block: 256 thr, 32 queries, K tiles of 64, dv=256.
// smem (floats): Q[32][128] | K 2x[64][132] | V 2x[64][256] | P2 u64[32][64]
// Scores: warp w -> queries 4w..4w+3; lane l -> keys {l, l+32}; f32x2 d-pairs.
// PV:     same queries; lane l -> dim-pairs {2l+64j}, j=0..3.
// =====================================================================
#define SELF_QOFF 0
#define SELF_KOFF 4096
#define SELF_KSTRIDE 8448           // 64*132
#define SELF_VOFF 20992
#define SELF_VSTRIDE 16384          // 64*256
#define SELF_P2OFF 53760            // float offset; u64[32][64]
#define SELF_NT   36

__device__ __forceinline__ void self_prefetch(float* sm, int buf, const float* wqs,
                                              const float* wvs, int k0, int tid)
{
    float* Kb = sm + SELF_KOFF + buf * SELF_KSTRIDE;
    float* Vb = sm + SELF_VOFF + buf * SELF_VSTRIDE;
#pragma unroll
    for (int r = 0; r < 8; r++) {                 // 2048 float4
        int idx = r * 256 + tid;
        int k = idx >> 5, u = idx & 31;
        cp16(Kb + k * 132 + 4 * u, wqs + (long)(k0 + k) * KD_ + 4 * u);
    }
#pragma unroll
    for (int r = 0; r < 16; r++) {                // 4096 float4
        int idx = r * 256 + tid;
        int k = idx >> 6, u = idx & 63;
        cp16(Vb + k * 256 + 4 * u, wvs + (long)(k0 + k) * C_ + 4 * u);
    }
}

__global__ void __launch_bounds__(256, 1)
self_attn_kernel(const float* __restrict__ wq, const float* __restrict__ wv,
                 const float* __restrict__ tgt, float* __restrict__ y)
{
    extern __shared__ float sm[];
    const int s = blockIdx.y, q0 = blockIdx.x * 32;
    const int tid = threadIdx.x, w = tid >> 5, l = tid & 31;
    const float* wqs = wq + (long)s * HW_ * KD_;
    const float* wvs = wv + (long)s * HW_ * C_;
    u64* P2 = reinterpret_cast<u64*>(sm + SELF_P2OFF);

    // stage Q (prescaled by TAU_INV)
    for (int idx = tid; idx < 32 * 32; idx += 256) {
        int q = idx >> 5, u = idx & 31;
        float4 v = *(const float4*)(wqs + (long)(q0 + q) * KD_ + 4 * u);
        v.x *= TAU_INV; v.y *= TAU_INV; v.z *= TAU_INV; v.w *= TAU_INV;
        *(float4*)(sm + SELF_QOFF + q * 128 + 4 * u) = v;
    }
    self_prefetch(sm, 0, wqs, wvs, 0, tid);
    CP_COMMIT();

    float l_run[4] = {0.f, 0.f, 0.f, 0.f};
    u64 accv[4][4];
#pragma unroll
    for (int i = 0; i < 4; i++)
#pragma unroll
        for (int jj = 0; jj < 4; jj++) accv[i][jj] = 0ull;

    for (int kt = 0; kt < SELF_NT; kt++) {
        const int cur = kt & 1;
        __syncthreads();                       // prev compute done -> safe to overwrite buf cur^1
        if (kt + 1 < SELF_NT)
            self_prefetch(sm, cur ^ 1, wqs, wvs, (kt + 1) * 64, tid);
        CP_COMMIT();
        CP_WAIT1();                            // tile kt resident
        __syncthreads();

        const float* Kb = sm + SELF_KOFF + cur * SELF_KSTRIDE;
        const float* Vb = sm + SELF_VOFF + cur * SELF_VSTRIDE;

        // ---- scores (d-pair f32x2) ----
        u64 sc[4][2];
#pragma unroll
        for (int i = 0; i < 4; i++) { sc[i][0] = 0ull; sc[i][1] = 0ull; }
#pragma unroll 8
        for (int u = 0; u < 32; u++) {
            ulonglong2 ka = *(const ulonglong2*)(Kb + l * 132 + 4 * u);
            ulonglong2 kb = *(const ulonglong2*)(Kb + (l + 32) * 132 + 4 * u);
#pragma unroll
            for (int i = 0; i < 4; i++) {
                ulonglong2 qv = *(const ulonglong2*)(sm + SELF_QOFF + (4 * w + i) * 128 + 4 * u);
                fma2(sc[i][0], qv.x, ka.x); fma2(sc[i][0], qv.y, ka.y);
                fma2(sc[i][1], qv.x, kb.x); fma2(sc[i][1], qv.y, kb.y);
            }
        }

        // ---- softmax: p = exp(s - 30) ----
#pragma unroll
        for (int i = 0; i < 4; i++) {
            float psum = 0.f;
#pragma unroll
            for (int m = 0; m < 2; m++) {
                float x, yv; unpack2(sc[i][m], x, yv);
                float p = __expf((x + yv) - 30.f);
                P2[(4 * w + i) * 64 + l + 32 * m] = pack2(p);
                psum += p;
            }
#pragma unroll
            for (int off = 16; off; off >>= 1)
                psum += __shfl_xor_sync(0xffffffffu, psum, off);
            l_run[i] += psum;
        }
        __syncwarp();

        // ---- PV ----
#pragma unroll 2
        for (int k = 0; k < 64; k++) {
            u64 p0 = P2[(4 * w + 0) * 64 + k];
            u64 p1 = P2[(4 * w + 1) * 64 + k];
            u64 p2v = P2[(4 * w + 2) * 64 + k];
            u64 p3 = P2[(4 * w + 3) * 64 + k];
            const float* vr = Vb + k * 256 + 2 * l;
#pragma unroll
            for (int jj = 0; jj < 4; jj++) {
                u64 vv = *(const u64*)(vr + 64 * jj);
                fma2(accv[0][jj], p0, vv);
                fma2(accv[1][jj], p1, vv);
                fma2(accv[2][jj], p2v, vv);
                fma2(accv[3][jj], p3, vv);
            }
        }
    }

    // epilogue: divide + residual
#pragma unroll
    for (int i = 0; i < 4; i++) {
        float inv = 1.f / l_run[i];
        int p = q0 + 4 * w + i;
#pragma unroll
        for (int jj = 0; jj < 4; jj++) {
            float x, yv; unpack2(accv[i][jj], x, yv);
            int d = 64 * jj + 2 * l;
            long b0 = ((long)(s * C_ + d)) * HW_ + p;
            y[b0]       = x * inv + tgt[b0];
            y[b0 + HW_] = yv * inv + tgt[b0 + HW_];
        }
    }
}

// =====================================================================
// InstanceNorm statistics over spatial axis (per s,c)
// =====================================================================
__global__ void instnorm_stats_kernel(const float* __restrict__ y,
                                      float* __restrict__ mu, float* __restrict__ rs)
{
    const int sc = blockIdx.x;
    const float* row = y + (long)sc * HW_;
    float sum = 0.f, ss = 0.f;
    for (int p = threadIdx.x; p < HW_; p += 256) {
        float v = row[p];
        sum += v; ss += v * v;
    }
    __shared__ float s1[256], s2[256];
    s1[threadIdx.x] = sum; s2[threadIdx.x] = ss;
    __syncthreads();
    for (int st = 128; st > 0; st >>= 1) {
        if (threadIdx.x < st) {
            s1[threadIdx.x] += s1[threadIdx.x + st];
            s2[threadIdx.x] += s2[threadIdx.x + st];
        }
        __syncthreads();
    }
    if (threadIdx.x == 0) {
        float m = s1[0] / (float)HW_;
        float var = s2[0] / (float)HW_ - m * m;
        mu[sc] = m;
        rs[sc] = rsqrtf(var + 1e-5f);
    }
}

__global__ void fold_kernel(const float* __restrict__ WK, const float* __restrict__ bK,
                            const float* __restrict__ mu, const float* __restrict__ rs,
                            float* __restrict__ Wf, float* __restrict__ bf)
{
    const int j = blockIdx.x, s = blockIdx.y, tid = threadIdx.x;
    float w = WK[j * C_ + tid] * rs[s * C_ + tid];
    Wf[((long)(s * KD_ + j)) * C_ + tid] = w;
    __shared__ float red[256];
    red[tid] = w * mu[s * C_ + tid];
    __syncthreads();
    for (int st = 128; st > 0; st >>= 1) {
        if (tid < st) red[tid] += red[tid + st];
        __syncthreads();
    }
    if (tid == 0) bf[s * KD_ + j] = bK[j] - red[0];
}

// =====================================================================
// Cross flash-attention, FUSED (fixed-max softmax, no P materialization).
// Block 256 thr, 32 queries, K tiles of 128, dv=16.
// smem (floats): Q[32][128] | K 2x[128][132] | V 2x[128][18]
// Thread: warp w -> queries 4w..4w+3; lane l -> keys {l+32m}, m=0..3.
// Each thread accumulates its keys' PV contribution for ALL 16 dims;
// one lane-butterfly reduction at the end.
// =====================================================================
#define CR_QOFF 0
#define CR_KOFF 4096
#define CR_KSTRIDE 16896            // 128*132
#define CR_VOFF 37888
#define CR_VSTRIDE 2304             // 128*18
#define CR_NT   90

__device__ __forceinline__ void cross_prefetch(float* sm, int buf, const float* wks,
                                               const float* wvs, int k0, int tid)
{
    float* Kb = sm + CR_KOFF + buf * CR_KSTRIDE;
    float* Vb = sm + CR_VOFF + buf * CR_VSTRIDE;
#pragma unroll
    for (int r = 0; r < 16; r++) {                // 4096 float4
        int idx = r * 256 + tid;
        int k = idx >> 5, u = idx & 31;
        cp16(Kb + k * 132 + 4 * u, wks + (long)(k0 + k) * KD_ + 4 * u);
    }
#pragma unroll
    for (int r = 0; r < 4; r++) {                 // 1024 u64
        int idx = r * 256 + tid;
        int k = idx >> 3, t = idx & 7;
        cp8(Vb + k * 18 + 2 * t, wvs + (long)(k0 + k) * CE_ + 2 * t);
    }
}

__global__ void __launch_bounds__(256, 1)
cross_attn_kernel(const float* __restrict__ wq2, const float* __restrict__ wk2,
                  const float* __restrict__ wv2, float* __restrict__ out)
{
    extern __shared__ float sm[];
    const int s = blockIdx.y, q0 = blockIdx.x * 32;
    const int tid = threadIdx.x, w = tid >> 5, l = tid & 31;
    const float* wqs = wq2 + (long)s * HW_ * KD_;
    const float* wks = wk2 + (long)s * LK_ * KD_;
    const float* wvs = wv2 + (long)s * LK_ * CE_;

    for (int idx = tid; idx < 32 * 32; idx += 256) {
        int q = idx >> 5, u = idx & 31;
        float4 v = *(const float4*)(wqs + (long)(q0 + q) * KD_ + 4 * u);
        v.x *= TAU_INV; v.y *= TAU_INV; v.z *= TAU_INV; v.w *= TAU_INV;
        *(float4*)(sm + CR_QOFF + q * 128 + 4 * u) = v;
    }
    cross_prefetch(sm, 0, wks, wvs, 0, tid);
    CP_COMMIT();

    float lsum[4] = {0.f, 0.f, 0.f, 0.f};
    u64 accv[4][8];
#pragma unroll
    for (int i = 0; i < 4; i++)
#pragma unroll
        for (int jj = 0; jj < 8; jj++) accv[i][jj] = 0ull;

    for (int kt = 0; kt < CR_NT; kt++) {
        const int cur = kt & 1;
        __syncthreads();
        if (kt + 1 < CR_NT)
            cross_prefetch(sm, cur ^ 1, wks, wvs, (kt + 1) * 128, tid);
        CP_COMMIT();
        CP_WAIT1();
        __syncthreads();

        const float* Kb = sm + CR_KOFF + cur * CR_KSTRIDE;
        const float* Vb = sm + CR_VOFF + cur * CR_VSTRIDE;

        // ---- scores: 4q x 4k per lane ----
        u64 sc[4][4];
#pragma unroll
        for (int i = 0; i < 4; i++)
#pragma unroll
            for (int m = 0; m < 4; m++) sc[i][m] = 0ull;

#pragma unroll 4
        for (int u = 0; u < 32; u++) {
            ulonglong2 kv[4];
#pragma unroll
            for (int m = 0; m < 4; m++)
                kv[m] = *(const ulonglong2*)(Kb + (l + 32 * m) * 132 + 4 * u);
#pragma unroll
            for (int i = 0; i < 4; i++) {
                ulonglong2 qv = *(const ulonglong2*)(sm + CR_QOFF + (4 * w + i) * 128 + 4 * u);
#pragma unroll
                for (int m = 0; m < 4; m++) {
                    fma2(sc[i][m], qv.x, kv[m].x);
                    fma2(sc[i][m], qv.y, kv[m].y);
                }
            }
        }

        // ---- softmax + PV, fused in registers ----
#pragma unroll
        for (int m = 0; m < 4; m++) {
            const int k = l + 32 * m;
            u64 pp[4];
#pragma unroll
            for (int i = 0; i < 4; i++) {
                float x, yv; unpack2(sc[i][m], x, yv);
                float p = __expf((x + yv) - 30.f);
                lsum[i] += p;
                pp[i] = pack2(p);
            }
            const float* vr = Vb + k * 18;
#pragma unroll
            for (int jj = 0; jj < 8; jj++) {
                u64 vv = *(const u64*)(vr + 2 * jj);
                fma2(accv[0][jj], pp[0], vv);
                fma2(accv[1][jj], pp[1], vv);
                fma2(accv[2][jj], pp[2], vv);
                fma2(accv[3][jj], pp[3], vv);
            }
        }
    }

    // ---- lane-butterfly reduction ----
#pragma unroll
    for (int off = 16; off; off >>= 1) {
#pragma unroll
        for (int i = 0; i < 4; i++) {
            lsum[i] += __shfl_xor_sync(0xffffffffu, lsum[i], off);
#pragma unroll
            for (int jj = 0; jj < 8; jj++)
                accv[i][jj] = add2(accv[i][jj],
                                   __shfl_xor_sync(0xffffffffu, accv[i][jj], off));
        }
    }
    if (l == 0) {
#pragma unroll
        for (int i = 0; i < 4; i++) {
            float inv = 1.f / lsum[i];
            int p = q0 + 4 * w + i;
#pragma unroll
            for (int jj = 0; jj < 8; jj++) {
                float x, yv; unpack2(accv[i][jj], x, yv);
                out[((long)(s * CE_ + 2 * jj    )) * HW_ + p] = x * inv;
                out[((long)(s * CE_ + 2 * jj + 1)) * HW_ + p] = yv * inv;
            }
        }
    }
}

// =====================================================================
// Launcher
// =====================================================================
extern "C" void kernel_launch(void* const* d_in, const int* in_sizes, int n_in,
                              void* d_out, int out_size)
{
    const float* tgt    = (const float*)d_in[0];
    const float* memory = (const float*)d_in[1];
    const float* pos    = (const float*)d_in[2];
    const float* WKs_w  = (const float*)d_in[3];
    const float* WKs_b  = (const float*)d_in[4];
    const float* WVs_w  = (const float*)d_in[5];
    const float* WVs_b  = (const float*)d_in[6];
    const float* WKc_w  = (const float*)d_in[7];
    const float* WKc_b  = (const float*)d_in[8];
    const float* WVc_w  = (const float*)d_in[9];
    const float* WVc_b  = (const float*)d_in[10];
    float* out = (float*)d_out;

    float *p_wq, *p_wv, *p_y, *p_wq2, *p_wk2, *p_wv2, *p_mu, *p_rs, *p_wf, *p_bf;
    cudaGetSymbolAddress((void**)&p_wq,  g_wq);
    cudaGetSymbolAddress((void**)&p_wv,  g_wv);
    cudaGetSymbolAddress((void**)&p_y,   g_y);
    cudaGetSymbolAddress((void**)&p_wq2, g_wq2);
    cudaGetSymbolAddress((void**)&p_wk2, g_wk2);
    cudaGetSymbolAddress((void**)&p_wv2, g_wv2);
    cudaGetSymbolAddress((void**)&p_mu,  g_mu);
    cudaGetSymbolAddress((void**)&p_rs,  g_rs);
    cudaGetSymbolAddress((void**)&p_wf,  g_wf);
    cudaGetSymbolAddress((void**)&p_bf,  g_bf);

    const int SELF_SH  = 57856 * 4;   // 231424 B
    const int CROSS_SH = 42496 * 4;   // 169984 B
    cudaFuncSetAttribute(self_attn_kernel,  cudaFuncAttributeMaxDynamicSharedMemorySize, SELF_SH);
    cudaFuncSetAttribute(cross_attn_kernel, cudaFuncAttributeMaxDynamicSharedMemorySize, CROSS_SH);

    // 1) self projections
    proj_kernel<128, 0, true ><<<dim3(HW_/16, S_), 256>>>(tgt, WKs_w, WKs_b, p_wq, C_, HW_, 0, 0);
    proj_kernel<256, 0, false><<<dim3(HW_/16, S_), 256>>>(tgt, WVs_w, WVs_b, p_wv, C_, HW_, 0, 0);
    // 2) self flash attention + residual -> g_y [s][c][p]
    self_attn_kernel<<<dim3(HW_/32, S_), 256, SELF_SH>>>(p_wq, p_wv, tgt, p_y);
    // 3) instance norm stats + fold into cross-K weights
    instnorm_stats_kernel<<<S_*C_, 256>>>(p_y, p_mu, p_rs);
    fold_kernel<<<dim3(KD_, S_), 256>>>(WKc_w, WKc_b, p_mu, p_rs, p_wf, p_bf);
    // 4) cross projections
    proj_kernel<128, 0, true ><<<dim3(HW_/16, S_), 256>>>(p_y, p_wf, p_bf, p_wq2, C_, HW_, KD_*C_, KD_);
    proj_kernel<128, 1, true ><<<dim3(LK_/16, S_), 256>>>(memory, WKc_w, WKc_b, p_wk2, C_, LK_, 0, 0);
    proj_kernel<16,  1, false><<<dim3(LK_/16, S_), 256>>>(pos, WVc_w, WVc_b, p_wv2, CE_, LK_, 0, 0);
    // 5) cross flash attention -> output [1,S,16,h,w]
    cross_attn_kernel<<<dim3(HW_/32, S_), 256, CROSS_SH>>>(p_wq2, p_wk2, p_wv2, out);
}